// round 2
// baseline (speedup 1.0000x reference)
#include <cuda_runtime.h>
#include <math.h>

#define NB   512
#define C0   256
#define M    80
#define PIX  676      // 26*26
#define PPIX 784      // 28*28
#define CHUNK 16

typedef unsigned long long ull;

__device__ float g_y [512u*256u*784u];   // deconv output (28x28)
__device__ float g_xp[512u*80u*676u];    // preproc output "x"
__device__ float g_h [512u*80u*676u];    // hidden state
__device__ float g_hg[512u*80u*676u];    // h * g1
__device__ float g_ns[512u*80u*676u];    // ns1

__device__ __forceinline__ float sigm_(float v) { return 1.f / (1.f + expf(-v)); }
__device__ __forceinline__ float sftp_(float v) { return fmaxf(v, 0.f) + log1pf(expf(-fabsf(v))); }

__device__ __forceinline__ ull pk2(float lo, float hi) {
    ull r; asm("mov.b64 %0, {%1, %2};" : "=l"(r) : "f"(lo), "f"(hi)); return r;
}
__device__ __forceinline__ void upk2(ull v, float& lo, float& hi) {
    asm("mov.b64 {%0, %1}, %2;" : "=f"(lo), "=f"(hi) : "l"(v));
}
__device__ __forceinline__ ull fma2(ull a, ull b, ull c) {
    ull d; asm("fma.rn.f32x2 %0, %1, %2, %3;" : "=l"(d) : "l"(a), "l"(b), "l"(c)); return d;
}

// ---------------------------------------------------------------------------
// Deconv 2x2 / stride 2 with f32x2.  Block: (8 input pixels, n); 256 thr = out ch.
// ---------------------------------------------------------------------------
__global__ __launch_bounds__(256) void k_deconv(const float* __restrict__ x,
                                                const float4* __restrict__ dw4,
                                                const float* __restrict__ db)
{
    __shared__ ull xs[8][256];           // input value duplicated into both halves
    const int n = blockIdx.y;
    const int pid0 = blockIdx.x * 8;
    const int tid = threadIdx.x;

    #pragma unroll
    for (int g = 0; g < 8; g++) {
        int pid = pid0 + g;
        float v = (pid < 196) ? x[(n*256 + tid)*196 + pid] : 0.f;
        xs[g][tid] = pk2(v, v);
    }
    __syncthreads();

    ull acc0[8], acc1[8];
    #pragma unroll
    for (int g = 0; g < 8; g++) { acc0[g] = 0ull; acc1[g] = 0ull; }

    for (int ch = 0; ch < 256; ch++) {
        float4 w = dw4[ch*256 + tid];
        ull w01 = pk2(w.x, w.y);
        ull w23 = pk2(w.z, w.w);
        #pragma unroll
        for (int g = 0; g < 8; g++) {
            ull xv = xs[g][ch];
            acc0[g] = fma2(xv, w01, acc0[g]);
            acc1[g] = fma2(xv, w23, acc1[g]);
        }
    }

    const float b = db[tid];
    #pragma unroll
    for (int g = 0; g < 8; g++) {
        int pid = pid0 + g;
        if (pid < 196) {
            int i = pid / 14, j = pid % 14;
            float* yp = &g_y[(n*256 + tid)*784 + (2*i)*28 + 2*j];
            float a0,a1,a2,a3; upk2(acc0[g],a0,a1); upk2(acc1[g],a2,a3);
            *(float2*)&yp[0]  = make_float2(a0 + b, a1 + b);
            *(float2*)&yp[28] = make_float2(a2 + b, a3 + b);
        }
    }
}

// ---------------------------------------------------------------------------
// t=0 shortcut: h = 0, ns1 = softplus(xp)
// ---------------------------------------------------------------------------
__global__ void k_init()
{
    int i = blockIdx.x*blockDim.x + threadIdx.x;
    if (i < NB*M*PIX) {
        g_h[i]  = 0.f;
        g_ns[i] = sftp_(g_xp[i]);
    }
}

// ---------------------------------------------------------------------------
// Gate 1 (1x1): hg = h * sigmoid(u1 . h + b1)  (unchanged from R1)
// ---------------------------------------------------------------------------
__global__ __launch_bounds__(256, 2) void k_gate1(const float* __restrict__ u1w,
                                                  const float* __restrict__ u1b)
{
    __shared__ float sw[M*M];
    __shared__ float sb[M];
    const int n = blockIdx.y, tid = threadIdx.x;

    for (int idx = tid; idx < M*M; idx += 256) sw[idx] = u1w[idx];
    if (tid < M) sb[tid] = u1b[tid];
    __syncthreads();

    const int p = blockIdx.x*256 + tid;
    if (p >= PIX) return;

    float hl[M];
    const float* hp = &g_h[n*M*PIX + p];
    #pragma unroll
    for (int c = 0; c < M; c++) hl[c] = hp[c*PIX];

    float* op = &g_hg[n*M*PIX + p];
    const float4* sw4 = (const float4*)sw;
    for (int m = 0; m < M; m++) {
        float acc = sb[m];
        #pragma unroll
        for (int c4 = 0; c4 < M/4; c4++) {
            float4 w = sw4[m*(M/4) + c4];
            acc = fmaf(hl[c4*4+0], w.x, acc);
            acc = fmaf(hl[c4*4+1], w.y, acc);
            acc = fmaf(hl[c4*4+2], w.z, acc);
            acc = fmaf(hl[c4*4+3], w.w, acc);
        }
        op[m*PIX] = hp[m*PIX] * sigm_(acc);
    }
}

// ---------------------------------------------------------------------------
// Unified 3x3 conv with f32x2 pixel-pairs.
//   EPI 0: preproc  (src = g_y, raw 28x28, CIN=256; out = g_xp + bias)
//   EPI 1: inh      (src = g_hg, padded;  ns1 = softplus(xp - c1*(alpha*h+mu)))
//   EPI 2: exc -> g_h   (fused u2 gate + GRU blend)
//   EPI 3: exc -> out
// Thread layout: 192 threads; tid -> (row y = tid/7, group g = tid%7, x0 = 4g)
// Each thread: 4 consecutive pixels (2 f32x2 pairs) x 8 output channels.
// ---------------------------------------------------------------------------
template<int CIN, int EPI>
__global__ __launch_bounds__(192, 2) void k_conv(const float* __restrict__ w,
                                                 const float* __restrict__ p0,
                                                 const float* __restrict__ p1,
                                                 float* __restrict__ out)
{
    extern __shared__ float sm[];
    float* sIn = sm;                                  // CHUNK*784 floats
    ull*   sWp = (ull*)(sm + CHUNK*PPIX);             // 8*CHUNK*10 pairs (dup)
    ull*   sU2 = sWp + 8*CHUNK*10;                    // 8*CHUNK pairs (dup)

    const int n = blockIdx.y, mt = blockIdx.x, tid = threadIdx.x;
    const bool act = tid < 182;
    const int y  = act ? tid / 7 : 0;
    const int x0 = act ? (tid % 7) * 4 : 0;
    const int g  = tid % 7;

    ull accA[8], accB[8];
    ull g2A[8], g2B[8];
    #pragma unroll
    for (int ml = 0; ml < 8; ml++) { accA[ml]=0ull; accB[ml]=0ull; g2A[ml]=0ull; g2B[ml]=0ull; }

    for (int cc0 = 0; cc0 < CIN; cc0 += CHUNK) {
        __syncthreads();
        // ---- stage input tile (28x28 per channel) ----
        if (EPI == 0) {
            for (int idx = tid; idx < CHUNK*PPIX; idx += 192) {
                int c = idx / PPIX, pp = idx - c*PPIX;
                sIn[idx] = g_y[(n*C0 + cc0 + c)*PPIX + pp];
            }
        } else {
            const float* srcp = (EPI == 1) ? g_hg : g_ns;
            for (int idx = tid; idx < CHUNK*PPIX; idx += 192) {
                int c = idx / PPIX, pp = idx - c*PPIX;
                int yy = pp / 28, xx = pp - yy*28;
                float v = 0.f;
                if (yy >= 1 && yy <= 26 && xx >= 1 && xx <= 26)
                    v = srcp[(n*M + cc0 + c)*PIX + (yy-1)*26 + (xx-1)];
                sIn[idx] = v;
            }
        }
        // ---- stage weights, duplicated into f32x2 pairs ----
        for (int idx = tid; idx < 8*CHUNK*9; idx += 192) {
            int ml = idx / (CHUNK*9), r = idx - ml*CHUNK*9;
            int c = r / 9, t = r - c*9;
            float wv = w[((mt*8 + ml)*CIN + cc0 + c)*9 + t];
            sWp[(ml*CHUNK + c)*10 + t] = pk2(wv, wv);
        }
        if (EPI >= 2 && tid < 8*CHUNK) {
            float uv = p0[(mt*8 + tid/CHUNK)*M + cc0 + (tid % CHUNK)];
            sU2[tid] = pk2(uv, uv);
        }
        __syncthreads();

        #pragma unroll 1
        for (int c = 0; c < CHUNK; c++) {
            // build sliding-window pairs for 3 rows
            ull P[3][5];
            #pragma unroll
            for (int r = 0; r < 3; r++) {
                const float4* rp = (const float4*)&sIn[c*PPIX + (y+r)*28 + x0];
                float4 A = rp[0], B = rp[1];
                P[r][0] = pk2(A.x, A.y);
                P[r][1] = pk2(A.y, A.z);
                P[r][2] = pk2(A.z, A.w);
                P[r][3] = pk2(A.w, B.x);
                P[r][4] = pk2(B.x, B.y);
            }
            #pragma unroll
            for (int ml = 0; ml < 8; ml++) {
                const ull* wp = &sWp[(ml*CHUNK + c)*10];
                #pragma unroll
                for (int t = 0; t < 9; t++) {
                    ull wv = wp[t];
                    accA[ml] = fma2(P[t/3][t%3],     wv, accA[ml]);
                    accB[ml] = fma2(P[t/3][t%3 + 2], wv, accB[ml]);
                }
                if (EPI >= 2) {
                    ull uv = sU2[ml*CHUNK + c];
                    g2A[ml] = fma2(P[1][1], uv, g2A[ml]);
                    g2B[ml] = fma2(P[1][3], uv, g2B[ml]);
                }
            }
        }
    }

    if (!act) return;
    const bool hasB = (g < 6);   // group 6 covers only pixels 24,25

    #pragma unroll
    for (int ml = 0; ml < 8; ml++) {
        const int m = mt*8 + ml;
        const int idx = (n*M + m)*PIX + y*26 + x0;
        float a0,a1,a2,a3; upk2(accA[ml],a0,a1); upk2(accB[ml],a2,a3);

        if (EPI == 0) {
            float b = p0[m];
            *(float2*)&g_xp[idx] = make_float2(a0 + b, a1 + b);
            if (hasB) *(float2*)&g_xp[idx+2] = make_float2(a2 + b, a3 + b);
        } else if (EPI == 1) {
            float al = p0[m], mm = p1[m];
            float2 h01 = *(const float2*)&g_h[idx];
            float2 x01 = *(const float2*)&g_xp[idx];
            *(float2*)&g_ns[idx] = make_float2(
                sftp_(x01.x - a0*(al*h01.x + mm)),
                sftp_(x01.y - a1*(al*h01.y + mm)));
            if (hasB) {
                float2 h23 = *(const float2*)&g_h[idx+2];
                float2 x23 = *(const float2*)&g_xp[idx+2];
                *(float2*)&g_ns[idx+2] = make_float2(
                    sftp_(x23.x - a2*(al*h23.x + mm)),
                    sftp_(x23.y - a3*(al*h23.y + mm)));
            }
        } else {
            float b2 = p1[m];
            float q0,q1,q2,q3; upk2(g2A[ml],q0,q1); upk2(g2B[ml],q2,q3);
            float* dst = (EPI == 3) ? out : g_h;
            float2 h01 = *(const float2*)&g_h[idx];
            float G0 = sigm_(q0 + b2), G1 = sigm_(q1 + b2);
            *(float2*)&dst[idx] = make_float2(
                (1.f - G0)*h01.x + G0*sftp_(a0),
                (1.f - G1)*h01.y + G1*sftp_(a1));
            if (hasB) {
                float2 h23 = *(const float2*)&g_h[idx+2];
                float G2 = sigm_(q2 + b2), G3 = sigm_(q3 + b2);
                *(float2*)&dst[idx+2] = make_float2(
                    (1.f - G2)*h23.x + G2*sftp_(a2),
                    (1.f - G3)*h23.y + G3*sftp_(a3));
            }
        }
    }
}

// ---------------------------------------------------------------------------
extern "C" void kernel_launch(void* const* d_in, const int* in_sizes, int n_in,
                              void* d_out, int out_size)
{
    const float* x        = (const float*)d_in[0];
    const float* deconv_w = (const float*)d_in[1];
    const float* deconv_b = (const float*)d_in[2];
    const float* pre_w    = (const float*)d_in[3];
    const float* pre_b    = (const float*)d_in[4];
    const float* u1_w     = (const float*)d_in[5];
    const float* u1_b     = (const float*)d_in[6];
    const float* u2_w     = (const float*)d_in[7];
    const float* u2_b     = (const float*)d_in[8];
    const float* w_inh    = (const float*)d_in[9];
    const float* w_exc    = (const float*)d_in[10];
    const float* alpha    = (const float*)d_in[11];
    const float* mu       = (const float*)d_in[12];
    float* out = (float*)d_out;

    const int smemC = CHUNK*PPIX*4 + 8*CHUNK*10*8 + 8*CHUNK*8;   // 61,440 B
    cudaFuncSetAttribute(k_conv<C0,0>, cudaFuncAttributeMaxDynamicSharedMemorySize, smemC);
    cudaFuncSetAttribute(k_conv<M, 1>, cudaFuncAttributeMaxDynamicSharedMemorySize, smemC);
    cudaFuncSetAttribute(k_conv<M, 2>, cudaFuncAttributeMaxDynamicSharedMemorySize, smemC);
    cudaFuncSetAttribute(k_conv<M, 3>, cudaFuncAttributeMaxDynamicSharedMemorySize, smemC);

    // Feedforward
    k_deconv<<<dim3(25, NB), 256>>>(x, (const float4*)deconv_w, deconv_b);
    k_conv<C0,0><<<dim3(10, NB), 192, smemC>>>(pre_w, pre_b, nullptr, nullptr);

    // t = 0 (h == 0 -> hg == 0 -> c1 == 0 -> ns1 = softplus(xp))
    k_init<<<(NB*M*PIX + 255)/256, 256>>>();
    k_conv<M,2><<<dim3(10, NB), 192, smemC>>>(w_exc, u2_w, u2_b, nullptr);

    // t = 1 .. 9
    for (int t = 1; t < 10; t++) {
        k_gate1  <<<dim3(3,  NB), 256>>>(u1_w, u1_b);
        k_conv<M,1><<<dim3(10, NB), 192, smemC>>>(w_inh, alpha, mu, nullptr);
        if (t < 9)
            k_conv<M,2><<<dim3(10, NB), 192, smemC>>>(w_exc, u2_w, u2_b, nullptr);
        else
            k_conv<M,3><<<dim3(10, NB), 192, smemC>>>(w_exc, u2_w, u2_b, out);
    }
}

// round 3
// speedup vs baseline: 1.2640x; 1.2640x over previous
#include <cuda_runtime.h>
#include <math.h>

#define NB   512
#define C0   256
#define M    80
#define PIX  676      // 26*26
#define PPIX 784      // 28*28
#define CHUNK 16
#define PTILE 420     // 15 packed rows * 28 cols (float2 entries per channel)

typedef unsigned long long ull;

__device__ float g_y [512u*256u*784u];   // deconv output (28x28)
__device__ float g_xp[512u*80u*676u];    // preproc output "x"
__device__ float g_h [512u*80u*676u];    // hidden state
__device__ float g_hg[512u*80u*676u];    // h * g1
__device__ float g_ns[512u*80u*676u];    // ns1

__device__ __forceinline__ float sigm_(float v) { return 1.f / (1.f + expf(-v)); }
__device__ __forceinline__ float sftp_(float v) { return fmaxf(v, 0.f) + log1pf(expf(-fabsf(v))); }

__device__ __forceinline__ ull pk2(float lo, float hi) {
    ull r; asm("mov.b64 %0, {%1, %2};" : "=l"(r) : "f"(lo), "f"(hi)); return r;
}
__device__ __forceinline__ void upk2(ull v, float& lo, float& hi) {
    asm("mov.b64 {%0, %1}, %2;" : "=f"(lo), "=f"(hi) : "l"(v));
}
__device__ __forceinline__ ull fma2(ull a, ull b, ull c) {
    ull d; asm("fma.rn.f32x2 %0, %1, %2, %3;" : "=l"(d) : "l"(a), "l"(b), "l"(c)); return d;
}

// ---------------------------------------------------------------------------
// Deconv 2x2 / stride 2 with f32x2 (weights born packed: (w00,w01),(w10,w11)).
// ---------------------------------------------------------------------------
__global__ __launch_bounds__(256) void k_deconv(const float* __restrict__ x,
                                                const float4* __restrict__ dw4,
                                                const float* __restrict__ db)
{
    __shared__ ull xs[8][256];
    const int n = blockIdx.y;
    const int pid0 = blockIdx.x * 8;
    const int tid = threadIdx.x;

    #pragma unroll
    for (int g = 0; g < 8; g++) {
        int pid = pid0 + g;
        float v = (pid < 196) ? x[(n*256 + tid)*196 + pid] : 0.f;
        xs[g][tid] = pk2(v, v);
    }
    __syncthreads();

    ull acc0[8], acc1[8];
    #pragma unroll
    for (int g = 0; g < 8; g++) { acc0[g] = 0ull; acc1[g] = 0ull; }

    for (int ch = 0; ch < 256; ch++) {
        float4 w = dw4[ch*256 + tid];
        ull w01 = pk2(w.x, w.y);
        ull w23 = pk2(w.z, w.w);
        #pragma unroll
        for (int g = 0; g < 8; g++) {
            ull xv = xs[g][ch];
            acc0[g] = fma2(xv, w01, acc0[g]);
            acc1[g] = fma2(xv, w23, acc1[g]);
        }
    }

    const float b = db[tid];
    #pragma unroll
    for (int g = 0; g < 8; g++) {
        int pid = pid0 + g;
        if (pid < 196) {
            int i = pid / 14, j = pid % 14;
            float* yp = &g_y[(n*256 + tid)*784 + (2*i)*28 + 2*j];
            float a0,a1,a2,a3; upk2(acc0[g],a0,a1); upk2(acc1[g],a2,a3);
            *(float2*)&yp[0]  = make_float2(a0 + b, a1 + b);
            *(float2*)&yp[28] = make_float2(a2 + b, a3 + b);
        }
    }
}

// ---------------------------------------------------------------------------
// t=0 shortcut: h = 0, ns1 = softplus(xp)
// ---------------------------------------------------------------------------
__global__ void k_init()
{
    int i = blockIdx.x*blockDim.x + threadIdx.x;
    if (i < NB*M*PIX) {
        g_h[i]  = 0.f;
        g_ns[i] = sftp_(g_xp[i]);
    }
}

// ---------------------------------------------------------------------------
// Gate 1 (1x1): hg = h * sigmoid(u1 . h + b1)
// ---------------------------------------------------------------------------
__global__ __launch_bounds__(256, 2) void k_gate1(const float* __restrict__ u1w,
                                                  const float* __restrict__ u1b)
{
    __shared__ float sw[M*M];
    __shared__ float sb[M];
    const int n = blockIdx.y, tid = threadIdx.x;

    for (int idx = tid; idx < M*M; idx += 256) sw[idx] = u1w[idx];
    if (tid < M) sb[tid] = u1b[tid];
    __syncthreads();

    const int p = blockIdx.x*256 + tid;
    if (p >= PIX) return;

    float hl[M];
    const float* hp = &g_h[n*M*PIX + p];
    #pragma unroll
    for (int c = 0; c < M; c++) hl[c] = hp[c*PIX];

    float* op = &g_hg[n*M*PIX + p];
    const float4* sw4 = (const float4*)sw;
    for (int m = 0; m < M; m++) {
        float acc = sb[m];
        #pragma unroll
        for (int c4 = 0; c4 < M/4; c4++) {
            float4 w = sw4[m*(M/4) + c4];
            acc = fmaf(hl[c4*4+0], w.x, acc);
            acc = fmaf(hl[c4*4+1], w.y, acc);
            acc = fmaf(hl[c4*4+2], w.z, acc);
            acc = fmaf(hl[c4*4+3], w.w, acc);
        }
        op[m*PIX] = hp[m*PIX] * sigm_(acc);
    }
}

// ---------------------------------------------------------------------------
// Unified 3x3 conv with *pre-packed* f32x2 smem layout:
// packed tile entry (r, x) = float2{ top_half(r,x), bottom_half(r,x) }.
// For SAME convs: packed row r holds img rows (r-1, r+12); col x holds img col x-1.
// For preproc (VALID on 28x28): packed row r holds rows (r, r+13); col x = x.
// Output packed row py covers out rows (py, py+13); 13x13 thread map.
//   EPI 0: preproc  (src g_y, CIN=256; out g_xp + bias)
//   EPI 1: inh      (src g_hg; ns1 = softplus(xp - c1*(alpha*h+mu)))
//   EPI 2: exc -> g_h   (fused u2 gate + GRU blend)
//   EPI 3: exc -> out
// ---------------------------------------------------------------------------
template<int CIN, int EPI>
__global__ __launch_bounds__(192, 2) void k_conv(const float* __restrict__ w,
                                                 const float* __restrict__ p0,
                                                 const float* __restrict__ p1,
                                                 float* __restrict__ out)
{
    extern __shared__ float sm[];
    float2* sIn2 = (float2*)sm;                        // CHUNK * 420 float2
    ull*    sWp  = (ull*)(sIn2 + CHUNK*PTILE);         // 8*CHUNK*10 dup pairs
    ull*    sU2  = sWp + 8*CHUNK*10;                   // 8*CHUNK dup pairs

    const int n = blockIdx.y, mt = blockIdx.x, tid = threadIdx.x;
    const bool act = tid < 169;
    const int py  = act ? tid / 13 : 0;        // packed output row 0..12
    const int px0 = act ? (tid % 13) * 2 : 0;  // packed output col {0,2,..,24}

    ull acc[8][2];
    ull g2 [8][2];
    #pragma unroll
    for (int ml = 0; ml < 8; ml++) {
        acc[ml][0]=0ull; acc[ml][1]=0ull; g2[ml][0]=0ull; g2[ml][1]=0ull;
    }

    for (int cc0 = 0; cc0 < CIN; cc0 += CHUNK) {
        __syncthreads();
        // ---- stage packed input tile ----
        if (EPI == 0) {
            for (int idx = tid; idx < CHUNK*PTILE; idx += 192) {
                int c = idx / PTILE, rem = idx - c*PTILE;
                int r = rem / 28, xx = rem - r*28;
                const float* s = &g_y[(ull)(n*C0 + cc0 + c)*PPIX];
                sIn2[idx] = make_float2(s[r*28 + xx], s[(r+13)*28 + xx]);
            }
        } else {
            const float* srcp = (EPI == 1) ? g_hg : g_ns;
            for (int idx = tid; idx < CHUNK*PTILE; idx += 192) {
                int c = idx / PTILE, rem = idx - c*PTILE;
                int r = rem / 28, xx = rem - r*28;
                int col = xx - 1;
                int tr = r - 1, br = r + 12;
                const float* s = &srcp[(ull)(n*M + cc0 + c)*PIX];
                bool colok = (unsigned)col < 26u;
                float vt = (colok && tr >= 0) ? s[tr*26 + col] : 0.f;
                float vb = (colok && br <= 25) ? s[br*26 + col] : 0.f;
                sIn2[idx] = make_float2(vt, vb);
            }
        }
        // ---- stage weights as duplicated pairs ----
        for (int idx = tid; idx < 8*CHUNK*9; idx += 192) {
            int ml = idx / (CHUNK*9), r = idx - ml*CHUNK*9;
            int c = r / 9, t = r - c*9;
            float wv = w[((mt*8 + ml)*CIN + cc0 + c)*9 + t];
            sWp[(ml*CHUNK + c)*10 + t] = pk2(wv, wv);
        }
        if (EPI >= 2 && tid < 8*CHUNK) {
            float uv = p0[(mt*8 + tid/CHUNK)*M + cc0 + (tid % CHUNK)];
            sU2[tid] = pk2(uv, uv);
        }
        __syncthreads();

        #pragma unroll 1
        for (int c = 0; c < CHUNK; c++) {
            // aligned packed window loads — NO repacking
            ull P[3][4];
            const float2* base = &sIn2[c*PTILE + py*28 + px0];
            #pragma unroll
            for (int r = 0; r < 3; r++) {
                const ulonglong2* rp = (const ulonglong2*)(base + r*28);
                ulonglong2 A = rp[0], B = rp[1];
                P[r][0] = A.x; P[r][1] = A.y; P[r][2] = B.x; P[r][3] = B.y;
            }
            #pragma unroll
            for (int ml = 0; ml < 8; ml++) {
                const ull* wp = &sWp[(ml*CHUNK + c)*10];
                #pragma unroll
                for (int t = 0; t < 9; t++) {
                    ull wv = wp[t];
                    acc[ml][0] = fma2(P[t/3][t%3],     wv, acc[ml][0]);
                    acc[ml][1] = fma2(P[t/3][t%3 + 1], wv, acc[ml][1]);
                }
                if (EPI >= 2) {
                    ull uv = sU2[ml*CHUNK + c];
                    g2[ml][0] = fma2(P[1][1], uv, g2[ml][0]);
                    g2[ml][1] = fma2(P[1][2], uv, g2[ml][1]);
                }
            }
        }
    }

    if (!act) return;

    #pragma unroll
    for (int ml = 0; ml < 8; ml++) {
        const int m = mt*8 + ml;
        const int it = (n*M + m)*PIX + py*26 + px0;          // top rows
        const int ib = it + 13*26;                           // bottom rows
        float t0,b0,t1,b1;
        upk2(acc[ml][0], t0, b0);   // (col px0)  top/bottom
        upk2(acc[ml][1], t1, b1);   // (col px0+1)

        if (EPI == 0) {
            float b = p0[m];
            *(float2*)&g_xp[it] = make_float2(t0 + b, t1 + b);
            *(float2*)&g_xp[ib] = make_float2(b0 + b, b1 + b);
        } else if (EPI == 1) {
            float al = p0[m], mm = p1[m];
            float2 ht = *(const float2*)&g_h[it];
            float2 xt = *(const float2*)&g_xp[it];
            *(float2*)&g_ns[it] = make_float2(
                sftp_(xt.x - t0*(al*ht.x + mm)),
                sftp_(xt.y - t1*(al*ht.y + mm)));
            float2 hb = *(const float2*)&g_h[ib];
            float2 xb = *(const float2*)&g_xp[ib];
            *(float2*)&g_ns[ib] = make_float2(
                sftp_(xb.x - b0*(al*hb.x + mm)),
                sftp_(xb.y - b1*(al*hb.y + mm)));
        } else {
            float b2 = p1[m];
            float q0,r0,q1,r1;
            upk2(g2[ml][0], q0, r0);
            upk2(g2[ml][1], q1, r1);
            float* dst = (EPI == 3) ? out : g_h;
            float2 ht = *(const float2*)&g_h[it];
            float G0 = sigm_(q0 + b2), G1 = sigm_(q1 + b2);
            *(float2*)&dst[it] = make_float2(
                (1.f - G0)*ht.x + G0*sftp_(t0),
                (1.f - G1)*ht.y + G1*sftp_(t1));
            float2 hb = *(const float2*)&g_h[ib];
            float H0 = sigm_(r0 + b2), H1 = sigm_(r1 + b2);
            *(float2*)&dst[ib] = make_float2(
                (1.f - H0)*hb.x + H0*sftp_(b0),
                (1.f - H1)*hb.y + H1*sftp_(b1));
        }
    }
}

// ---------------------------------------------------------------------------
extern "C" void kernel_launch(void* const* d_in, const int* in_sizes, int n_in,
                              void* d_out, int out_size)
{
    const float* x        = (const float*)d_in[0];
    const float* deconv_w = (const float*)d_in[1];
    const float* deconv_b = (const float*)d_in[2];
    const float* pre_w    = (const float*)d_in[3];
    const float* pre_b    = (const float*)d_in[4];
    const float* u1_w     = (const float*)d_in[5];
    const float* u1_b     = (const float*)d_in[6];
    const float* u2_w     = (const float*)d_in[7];
    const float* u2_b     = (const float*)d_in[8];
    const float* w_inh    = (const float*)d_in[9];
    const float* w_exc    = (const float*)d_in[10];
    const float* alpha    = (const float*)d_in[11];
    const float* mu       = (const float*)d_in[12];
    float* out = (float*)d_out;

    const int smemC = CHUNK*PTILE*8 + 8*CHUNK*10*8 + 8*CHUNK*8;   // 65,024 B
    cudaFuncSetAttribute(k_conv<C0,0>, cudaFuncAttributeMaxDynamicSharedMemorySize, smemC);
    cudaFuncSetAttribute(k_conv<M, 1>, cudaFuncAttributeMaxDynamicSharedMemorySize, smemC);
    cudaFuncSetAttribute(k_conv<M, 2>, cudaFuncAttributeMaxDynamicSharedMemorySize, smemC);
    cudaFuncSetAttribute(k_conv<M, 3>, cudaFuncAttributeMaxDynamicSharedMemorySize, smemC);

    // Feedforward
    k_deconv<<<dim3(25, NB), 256>>>(x, (const float4*)deconv_w, deconv_b);
    k_conv<C0,0><<<dim3(10, NB), 192, smemC>>>(pre_w, pre_b, nullptr, nullptr);

    // t = 0 (h == 0 -> hg == 0 -> c1 == 0 -> ns1 = softplus(xp))
    k_init<<<(NB*M*PIX + 255)/256, 256>>>();
    k_conv<M,2><<<dim3(10, NB), 192, smemC>>>(w_exc, u2_w, u2_b, nullptr);

    // t = 1 .. 9
    for (int t = 1; t < 10; t++) {
        k_gate1  <<<dim3(3,  NB), 256>>>(u1_w, u1_b);
        k_conv<M,1><<<dim3(10, NB), 192, smemC>>>(w_inh, alpha, mu, nullptr);
        if (t < 9)
            k_conv<M,2><<<dim3(10, NB), 192, smemC>>>(w_exc, u2_w, u2_b, nullptr);
        else
            k_conv<M,3><<<dim3(10, NB), 192, smemC>>>(w_exc, u2_w, u2_b, out);
    }
}